// round 8
// baseline (speedup 1.0000x reference)
#include <cuda_runtime.h>

#define HD 90
#define SD 30
#define VD 16
#define NBINS (HD * SD * VD)
#define HW_SHIFT 20
#define HW (1 << HW_SHIFT)

// One packed u32 per bin: [31:20] hue u12 (dh*64 + 2048), [19:10] (sat-1)*1024+512,
// [9:0] (val-1)*1024+512. Table (+1 pad entry) = 172.8 KB in smem;
// 8 LDS.32 per pixel fetch all 24 trilinear corner values.
__device__ unsigned int g_tab[NBINS + 1];

__global__ void prep_kernel(const float* __restrict__ lut) {
    int bin = blockIdx.x * blockDim.x + threadIdx.x;
    if (bin > NBINS) return;
    int src = (bin == NBINS) ? NBINS - 1 : bin;   // pad entry: finite duplicate
    const float* e = lut + (size_t)src * 3;
    int qh = __float2int_rn(e[0] * 64.0f) + 2048;            // step 1/64 deg
    int qs = __float2int_rn((e[1] - 1.0f) * 1024.0f) + 512;  // step 2^-10
    int qv = __float2int_rn((e[2] - 1.0f) * 1024.0f) + 512;
    qh = min(max(qh, 0), 4095);
    qs = min(max(qs, 0), 1023);
    qv = min(max(qv, 0), 1023);
    g_tab[bin] = ((unsigned)qh << 20) | ((unsigned)qs << 10) | (unsigned)qv;
}

__device__ __forceinline__ float rcp_approx(float x) {
    float y;
    asm("rcp.approx.f32 %0, %1;" : "=f"(y) : "f"(x));
    return y;
}

// Field extraction: shifts done as IMAD.HI (__umulhi -> FMA pipe), masking+bias
// OR fused into single LOP3s (ALU pipe). 2 IMAD.HI + 3 LOP3 per word.
#define HBIAS 8390656.0f   /* 8388608 + 2048 */
#define SBIAS 8389120.0f   /* 8388608 + 512  */

__device__ __forceinline__ void extract3(unsigned w, float& fh_, float& fs_, float& fv_) {
    unsigned th = __umulhi(w, 1u << 12);   // w >> 20  (IMAD.HI, FMA pipe)
    unsigned ts = __umulhi(w, 1u << 22);   // w >> 10
    fh_ = __uint_as_float(th | 0x4B000000u);                 // LOP3
    fs_ = __uint_as_float((ts & 0x3FFu) | 0x4B000000u);      // LOP3
    fv_ = __uint_as_float((w  & 0x3FFu) | 0x4B000000u);      // LOP3
}

__device__ __forceinline__ void process_pixel(const unsigned int* __restrict__ s_t,
                                              float r, float g, float b,
                                              float& o0, float& o1, float& o2) {
    const float EPS = 1e-8f;
    r = __saturatef(r); g = __saturatef(g); b = __saturatef(b);

    // ---- rgb2hsv, hue kept in hp-units (h/60, range [0,6]) ----
    float cmax  = fmaxf(r, fmaxf(g, b));
    float cmin  = fminf(r, fminf(g, b));
    float delta = cmax - cmin;
    float rd = rcp_approx(delta + EPS);

    float q = (g - b) * rd;
    if (q < 0.0f) q += 6.0f;                    // floor-mod 6; can round to 6.0!
    float hraw = (cmax == r) ? q
               : (cmax == g) ? (b - r) * rd + 2.0f
                             : (r - g) * rd + 4.0f;
    if (delta <= EPS) hraw = 0.0f;
    float s = (cmax > EPS) ? delta * rcp_approx(cmax + EPS) : 0.0f;
    float v = cmax;

    // ---- lookup indices ----
    float hs  = hraw * 15.0f;                   // in [0, 90] (90 iff hraw rounded to 6)
    float h0f = floorf(hs);
    float fh  = hs - h0f;
    int i0 = (int)h0f;
    if (i0 >= HD) i0 = 0;                       // hs==90 -> bin 0, fh==0 (ref: 360%360)

    float ssv = fminf(s, 1.0f) * (float)(SD - 1);
    float s0f = fminf(floorf(ssv), 28.0f);      // clamp: j1<=29 always valid
    float fs  = ssv - s0f;
    int j0 = (int)s0f;

    float vsv = v * (float)(VD - 1);
    float v0f = floorf(vsv);
    float fv  = vsv - v0f;                      // at v==1: fv==0, +1 hits pad

    int b00 = (i0 * SD + j0) * VD + (int)v0f;
    int di = (i0 == HD - 1) ? -(HD - 1) * SD * VD : SD * VD;
    int b01 = b00 + VD;
    int b10 = b00 + di;
    int b11 = b10 + VD;

    // ---- 8 LDS.32: all 24 corner values ----
    unsigned w00a = s_t[b00], w00b = s_t[b00 + 1];
    unsigned w01a = s_t[b01], w01b = s_t[b01 + 1];
    unsigned w10a = s_t[b10], w10b = s_t[b10 + 1];
    unsigned w11a = s_t[b11], w11b = s_t[b11 + 1];

    float ha00,sa00,va00, hb00,sb00,vb00;
    float ha01,sa01,va01, hb01,sb01,vb01;
    float ha10,sa10,va10, hb10,sb10,vb10;
    float ha11,sa11,va11, hb11,sb11,vb11;
    extract3(w00a, ha00, sa00, va00);  extract3(w00b, hb00, sb00, vb00);
    extract3(w01a, ha01, sa01, va01);  extract3(w01b, hb01, sb01, vb01);
    extract3(w10a, ha10, sa10, va10);  extract3(w10b, hb10, sb10, vb10);
    extract3(w11a, ha11, sa11, va11);  extract3(w11b, hb11, sb11, vb11);

    // exact raw-domain v-lerps: d = fb-fa exact; result = fma(fv, d, fa-bias)
    float hc00 = fmaf(fv, hb00 - ha00, ha00 - HBIAS);
    float hc01 = fmaf(fv, hb01 - ha01, ha01 - HBIAS);
    float hc10 = fmaf(fv, hb10 - ha10, ha10 - HBIAS);
    float hc11 = fmaf(fv, hb11 - ha11, ha11 - HBIAS);
    float sc00 = fmaf(fv, sb00 - sa00, sa00 - SBIAS);
    float sc01 = fmaf(fv, sb01 - sa01, sa01 - SBIAS);
    float sc10 = fmaf(fv, sb10 - sa10, sa10 - SBIAS);
    float sc11 = fmaf(fv, sb11 - sa11, sa11 - SBIAS);
    float vc00 = fmaf(fv, vb00 - va00, va00 - SBIAS);
    float vc01 = fmaf(fv, vb01 - va01, va01 - SBIAS);
    float vc10 = fmaf(fv, vb10 - va10, va10 - SBIAS);
    float vc11 = fmaf(fv, vb11 - va11, va11 - SBIAS);

    // weights: 5 ops
    float w11w = fh * fs;
    float w10w = fh - w11w;          // fh*(1-fs)
    float w01w = fs - w11w;          // (1-fh)*fs
    float w00w = (1.0f - fh) - w01w; // (1-fh)*(1-fs)

    float dhr = w00w * hc00 + w01w * hc01 + w10w * hc10 + w11w * hc11;  // dh*64 (deg)
    float smr = w00w * sc00 + w01w * sc01 + w10w * sc10 + w11w * sc11;  // (sm-1)*1024
    float vmr = w00w * vc00 + w01w * vc01 + w10w * vc10 + w11w * vc11;

    // hue update directly in hp units: dh_hp = dhr/(64*60)
    float hp = fmaf(dhr, 1.0f / 3840.0f, hraw);
    if (hp < 0.0f)  hp += 6.0f;
    if (hp >= 6.0f) hp -= 6.0f;      // hp in [0,6)
    float s2 = __saturatef(fmaf(smr, s * 0.0009765625f, s));
    float v2 = __saturatef(fmaf(vmr, v * 0.0009765625f, v));

    // ---- hsv2rgb ----
    float cc  = v2 * s2;
    float hpm = hp - 2.0f * floorf(hp * 0.5f);
    float xx  = cc * (1.0f - fabsf(hpm - 1.0f));
    float m   = v2 - cc;
    int sec = (int)hp;               // [0,5]
    if (sec > 5) sec = 5;            // paranoia vs fp edge; 1 IMNMX

    float rr = (sec == 0 || sec == 5) ? cc : ((sec == 1 || sec == 4) ? xx : 0.0f);
    float gg = (sec == 1 || sec == 2) ? cc : ((sec == 0 || sec == 3) ? xx : 0.0f);
    float bb = (sec == 3 || sec == 4) ? cc : ((sec == 2 || sec == 5) ? xx : 0.0f);
    rr += m; gg += m; bb += m;

    // ---- einsum RGB2XYZ_D50 + clip ----
    o0 = __saturatef(0.7976749f * rr + 0.1351917f * gg + 0.0313534f  * bb);
    o1 = __saturatef(0.2880402f * rr + 0.7118741f * gg + 8.57e-05f   * bb);
    o2 = __saturatef(0.82521f * bb);
}

__global__ __launch_bounds__(1024, 1)
void ProfileLookTableEncoding_kernel(const float* __restrict__ x,
                                     float* __restrict__ out, int nquads) {
    extern __shared__ unsigned int s_t[];

    for (int idx = threadIdx.x; idx < NBINS + 1; idx += 1024)
        s_t[idx] = g_tab[idx];
    __syncthreads();

    int stride = gridDim.x * 1024;
    for (int t = blockIdx.x * 1024 + threadIdx.x; t < nquads; t += stride) {
        int p = t * 4;
        int bidx = p >> HW_SHIFT;
        int hw   = p & (HW - 1);
        size_t base = (size_t)bidx * 3 * HW + hw;

        float4 R4 = *reinterpret_cast<const float4*>(x + base);
        float4 G4 = *reinterpret_cast<const float4*>(x + base + HW);
        float4 B4 = *reinterpret_cast<const float4*>(x + base + 2 * HW);

        float rr[4] = {R4.x, R4.y, R4.z, R4.w};
        float gg[4] = {G4.x, G4.y, G4.z, G4.w};
        float bb[4] = {B4.x, B4.y, B4.z, B4.w};
        float o0[4], o1[4], o2[4];

#pragma unroll
        for (int u = 0; u < 4; u++) {
            process_pixel(s_t, rr[u], gg[u], bb[u], o0[u], o1[u], o2[u]);
        }

        float4 O0 = {o0[0], o0[1], o0[2], o0[3]};
        float4 O1 = {o1[0], o1[1], o1[2], o1[3]};
        float4 O2 = {o2[0], o2[1], o2[2], o2[3]};
        *reinterpret_cast<float4*>(out + base)          = O0;
        *reinterpret_cast<float4*>(out + base + HW)     = O1;
        *reinterpret_cast<float4*>(out + base + 2 * HW) = O2;
    }
}

extern "C" void kernel_launch(void* const* d_in, const int* in_sizes, int n_in,
                              void* d_out, int out_size) {
    const float* x   = (const float*)d_in[0];
    const float* lut = (const float*)d_in[1];
    float* out = (float*)d_out;

    prep_kernel<<<(NBINS + 1 + 255) / 256, 256>>>(lut);

    int dev = 0, nsm = 148;
    cudaGetDevice(&dev);
    cudaDeviceGetAttribute(&nsm, cudaDevAttrMultiProcessorCount, dev);

    const int smem_bytes = (NBINS + 1) * (int)sizeof(unsigned int);
    cudaFuncSetAttribute(ProfileLookTableEncoding_kernel,
                         cudaFuncAttributeMaxDynamicSharedMemorySize, smem_bytes);

    int npix = in_sizes[0] / 3;          // 8 * 1024 * 1024
    int nquads = npix / 4;
    ProfileLookTableEncoding_kernel<<<nsm, 1024, smem_bytes>>>(x, out, nquads);
}

// round 9
// speedup vs baseline: 1.0985x; 1.0985x over previous
#include <cuda_runtime.h>

#define HD 90
#define SD 30
#define VD 16
#define NBINS (HD * SD * VD)
#define HW_SHIFT 20
#define HW (1 << HW_SHIFT)

// One packed u32 per bin: [31:20] hue u12 (dh*64 + 2048), [19:10] (sat-1)*1024+512,
// [9:0] (val-1)*1024+512. Table (+pad to uint4 multiple) lives in smem;
// 8 LDS.32 per pixel fetch all 24 trilinear corner values.
#define NBINS_PAD 43204   /* NBINS+1 rounded up to multiple of 4 */
__device__ unsigned int g_tab[NBINS_PAD];

__global__ void prep_kernel(const float* __restrict__ lut) {
    int bin = blockIdx.x * blockDim.x + threadIdx.x;
    if (bin >= NBINS_PAD) return;
    int src = (bin >= NBINS) ? NBINS - 1 : bin;   // pad entries: finite duplicates
    const float* e = lut + (size_t)src * 3;
    int qh = __float2int_rn(e[0] * 64.0f) + 2048;            // step 1/64 deg
    int qs = __float2int_rn((e[1] - 1.0f) * 1024.0f) + 512;  // step 2^-10
    int qv = __float2int_rn((e[2] - 1.0f) * 1024.0f) + 512;
    qh = min(max(qh, 0), 4095);
    qs = min(max(qs, 0), 1023);
    qv = min(max(qv, 0), 1023);
    g_tab[bin] = ((unsigned)qh << 20) | ((unsigned)qs << 10) | (unsigned)qv;
}

__device__ __forceinline__ float rcp_approx(float x) {
    float y;
    asm("rcp.approx.f32 %0, %1;" : "=f"(y) : "f"(x));
    return y;
}

#define HBIAS 8390656.0f   /* 8388608 + 2048 */
#define SBIAS 8389120.0f   /* 8388608 + 512  */

// 2 SHF + 3 LOP3 per word (plain shifts; umulhi variant regressed in R8)
__device__ __forceinline__ void extract3(unsigned w, float& fh_, float& fs_, float& fv_) {
    fh_ = __uint_as_float((w >> 20)            | 0x4B000000u);
    fs_ = __uint_as_float(((w >> 10) & 0x3FFu) | 0x4B000000u);
    fv_ = __uint_as_float((w         & 0x3FFu) | 0x4B000000u);
}

__device__ __forceinline__ void process_pixel(const unsigned int* __restrict__ s_t,
                                              float r, float g, float b,
                                              float& o0, float& o1, float& o2) {
    const float EPS = 1e-8f;
    r = __saturatef(r); g = __saturatef(g); b = __saturatef(b);

    // ---- rgb2hsv, hue kept in hp-units (h/60, range [0,6]) ----
    float cmax  = fmaxf(r, fmaxf(g, b));
    float cmin  = fminf(r, fminf(g, b));
    float delta = cmax - cmin;
    float rd = rcp_approx(delta + EPS);

    float q = (g - b) * rd;
    if (q < 0.0f) q += 6.0f;                    // floor-mod 6; may round to 6.0
    float hraw = (cmax == r) ? q
               : (cmax == g) ? (b - r) * rd + 2.0f
                             : (r - g) * rd + 4.0f;
    if (delta <= EPS) hraw = 0.0f;
    float s = (cmax > EPS) ? delta * rcp_approx(cmax + EPS) : 0.0f;
    float v = cmax;

    // ---- lookup indices ----
    float hs  = hraw * 15.0f;                   // [0,90]; 90 iff hraw rounded to 6
    float h0f = floorf(hs);
    float fh  = hs - h0f;
    int i0 = (int)h0f;
    if (i0 >= HD) i0 = 0;                       // hs==90 -> bin 0, fh==0 (ref 360%360)

    float ssv = fminf(s, 1.0f) * (float)(SD - 1);
    float s0f = fminf(floorf(ssv), 28.0f);      // clamp: j1<=29 always valid
    float fs  = ssv - s0f;
    int j0 = (int)s0f;

    float vsv = v * (float)(VD - 1);
    float v0f = floorf(vsv);
    float fv  = vsv - v0f;                      // v==1: fv==0, +1 hits pad

    int b00 = (i0 * SD + j0) * VD + (int)v0f;
    int di = (i0 == HD - 1) ? -(HD - 1) * SD * VD : SD * VD;
    int b01 = b00 + VD;
    int b10 = b00 + di;
    int b11 = b10 + VD;

    // ---- 8 LDS.32: all 24 corner values ----
    unsigned w00a = s_t[b00], w00b = s_t[b00 + 1];
    unsigned w01a = s_t[b01], w01b = s_t[b01 + 1];
    unsigned w10a = s_t[b10], w10b = s_t[b10 + 1];
    unsigned w11a = s_t[b11], w11b = s_t[b11 + 1];

    float ha00,sa00,va00, hb00,sb00,vb00;
    float ha01,sa01,va01, hb01,sb01,vb01;
    float ha10,sa10,va10, hb10,sb10,vb10;
    float ha11,sa11,va11, hb11,sb11,vb11;
    extract3(w00a, ha00, sa00, va00);  extract3(w00b, hb00, sb00, vb00);
    extract3(w01a, ha01, sa01, va01);  extract3(w01b, hb01, sb01, vb01);
    extract3(w10a, ha10, sa10, va10);  extract3(w10b, hb10, sb10, vb10);
    extract3(w11a, ha11, sa11, va11);  extract3(w11b, hb11, sb11, vb11);

    // exact raw-domain v-lerps: d = fb-fa exact; result = fma(fv, d, fa-bias)
    float hc00 = fmaf(fv, hb00 - ha00, ha00 - HBIAS);
    float hc01 = fmaf(fv, hb01 - ha01, ha01 - HBIAS);
    float hc10 = fmaf(fv, hb10 - ha10, ha10 - HBIAS);
    float hc11 = fmaf(fv, hb11 - ha11, ha11 - HBIAS);
    float sc00 = fmaf(fv, sb00 - sa00, sa00 - SBIAS);
    float sc01 = fmaf(fv, sb01 - sa01, sa01 - SBIAS);
    float sc10 = fmaf(fv, sb10 - sa10, sa10 - SBIAS);
    float sc11 = fmaf(fv, sb11 - sa11, sa11 - SBIAS);
    float vc00 = fmaf(fv, vb00 - va00, va00 - SBIAS);
    float vc01 = fmaf(fv, vb01 - va01, va01 - SBIAS);
    float vc10 = fmaf(fv, vb10 - va10, va10 - SBIAS);
    float vc11 = fmaf(fv, vb11 - va11, va11 - SBIAS);

    // weights: 5 ops
    float w11w = fh * fs;
    float w10w = fh - w11w;          // fh*(1-fs)
    float w01w = fs - w11w;          // (1-fh)*fs
    float w00w = (1.0f - fh) - w01w; // (1-fh)*(1-fs)

    float dhr = w00w * hc00 + w01w * hc01 + w10w * hc10 + w11w * hc11;  // dh*64 (deg)
    float smr = w00w * sc00 + w01w * sc01 + w10w * sc10 + w11w * sc11;  // (sm-1)*1024
    float vmr = w00w * vc00 + w01w * vc01 + w10w * vc10 + w11w * vc11;

    // hue update in hp units: dh_hp = dhr/(64*60)
    float hp = fmaf(dhr, 1.0f / 3840.0f, hraw);
    if (hp < 0.0f)  hp += 6.0f;
    if (hp >= 6.0f) hp -= 6.0f;
    float s2 = __saturatef(fmaf(smr, s * 0.0009765625f, s));
    float v2 = __saturatef(fmaf(vmr, v * 0.0009765625f, v));

    // ---- hsv2rgb ----
    float cc  = v2 * s2;
    float hpm = hp - 2.0f * floorf(hp * 0.5f);
    float xx  = cc * (1.0f - fabsf(hpm - 1.0f));
    float m   = v2 - cc;
    int sec = (int)hp;
    if (sec > 5) sec = 5;            // fp edge (hp snapped to 6.0): xx==0 there

    float rr = (sec == 0 || sec == 5) ? cc : ((sec == 1 || sec == 4) ? xx : 0.0f);
    float gg = (sec == 1 || sec == 2) ? cc : ((sec == 0 || sec == 3) ? xx : 0.0f);
    float bb = (sec == 3 || sec == 4) ? cc : ((sec == 2 || sec == 5) ? xx : 0.0f);
    rr += m; gg += m; bb += m;

    // ---- einsum RGB2XYZ_D50 + clip ----
    o0 = __saturatef(0.7976749f * rr + 0.1351917f * gg + 0.0313534f  * bb);
    o1 = __saturatef(0.2880402f * rr + 0.7118741f * gg + 8.57e-05f   * bb);
    o2 = __saturatef(0.82521f * bb);
}

__global__ __launch_bounds__(1024, 1)
void ProfileLookTableEncoding_kernel(const float* __restrict__ x,
                                     float* __restrict__ out, int nquads) {
    extern __shared__ unsigned int s_t[];

    // Preload packed table into smem, uint4-wide (NBINS_PAD % 4 == 0)
    {
        const uint4* src = reinterpret_cast<const uint4*>(g_tab);
        uint4* dst = reinterpret_cast<uint4*>(s_t);
        for (int idx = threadIdx.x; idx < NBINS_PAD / 4; idx += 1024)
            dst[idx] = src[idx];
    }
    __syncthreads();

    int stride = gridDim.x * 1024;
    for (int t = blockIdx.x * 1024 + threadIdx.x; t < nquads; t += stride) {
        int p = t * 4;
        int bidx = p >> HW_SHIFT;
        int hw   = p & (HW - 1);
        size_t base = (size_t)bidx * 3 * HW + hw;

        float4 R4 = *reinterpret_cast<const float4*>(x + base);
        float4 G4 = *reinterpret_cast<const float4*>(x + base + HW);
        float4 B4 = *reinterpret_cast<const float4*>(x + base + 2 * HW);

        float rr[4] = {R4.x, R4.y, R4.z, R4.w};
        float gg[4] = {G4.x, G4.y, G4.z, G4.w};
        float bb[4] = {B4.x, B4.y, B4.z, B4.w};
        float o0[4], o1[4], o2[4];

#pragma unroll
        for (int u = 0; u < 4; u++) {
            process_pixel(s_t, rr[u], gg[u], bb[u], o0[u], o1[u], o2[u]);
        }

        float4 O0 = {o0[0], o0[1], o0[2], o0[3]};
        float4 O1 = {o1[0], o1[1], o1[2], o1[3]};
        float4 O2 = {o2[0], o2[1], o2[2], o2[3]};
        *reinterpret_cast<float4*>(out + base)          = O0;
        *reinterpret_cast<float4*>(out + base + HW)     = O1;
        *reinterpret_cast<float4*>(out + base + 2 * HW) = O2;
    }
}

extern "C" void kernel_launch(void* const* d_in, const int* in_sizes, int n_in,
                              void* d_out, int out_size) {
    const float* x   = (const float*)d_in[0];
    const float* lut = (const float*)d_in[1];
    float* out = (float*)d_out;

    prep_kernel<<<(NBINS_PAD + 255) / 256, 256>>>(lut);

    int dev = 0, nsm = 148;
    cudaGetDevice(&dev);
    cudaDeviceGetAttribute(&nsm, cudaDevAttrMultiProcessorCount, dev);

    const int smem_bytes = NBINS_PAD * (int)sizeof(unsigned int);  // 172816 B
    cudaFuncSetAttribute(ProfileLookTableEncoding_kernel,
                         cudaFuncAttributeMaxDynamicSharedMemorySize, smem_bytes);

    int npix = in_sizes[0] / 3;          // 8 * 1024 * 1024
    int nquads = npix / 4;
    ProfileLookTableEncoding_kernel<<<nsm, 1024, smem_bytes>>>(x, out, nquads);
}

// round 10
// speedup vs baseline: 1.2210x; 1.1115x over previous
#include <cuda_runtime.h>

#define HD 90
#define SD 30
#define VD 16
#define NBINS (HD * SD * VD)
#define HW_SHIFT 20
#define HW (1 << HW_SHIFT)

// One packed u32 per bin: [31:20] hue u12 (dh*64 + 2048), [19:10] (sat-1)*1024+512,
// [9:0] (val-1)*1024+512. Table (+pad to uint4 multiple) lives in smem;
// 8 LDS.32 per pixel fetch all 24 trilinear corner values.
#define NBINS_PAD 43204   /* NBINS+1 rounded up to multiple of 4 */
__device__ unsigned int g_tab[NBINS_PAD];

__global__ void prep_kernel(const float* __restrict__ lut) {
    int bin = blockIdx.x * blockDim.x + threadIdx.x;
    if (bin >= NBINS_PAD) return;
    int src = (bin >= NBINS) ? NBINS - 1 : bin;   // pad entries: finite duplicates
    const float* e = lut + (size_t)src * 3;
    int qh = __float2int_rn(e[0] * 64.0f) + 2048;            // step 1/64 deg
    int qs = __float2int_rn((e[1] - 1.0f) * 1024.0f) + 512;  // step 2^-10
    int qv = __float2int_rn((e[2] - 1.0f) * 1024.0f) + 512;
    qh = min(max(qh, 0), 4095);
    qs = min(max(qs, 0), 1023);
    qv = min(max(qv, 0), 1023);
    g_tab[bin] = ((unsigned)qh << 20) | ((unsigned)qs << 10) | (unsigned)qv;
}

__device__ __forceinline__ float rcp_approx(float x) {
    float y;
    asm("rcp.approx.f32 %0, %1;" : "=f"(y) : "f"(x));
    return y;
}

#define HBIAS 8390656.0f   /* 8388608 + 2048 */
#define SBIAS 8389120.0f   /* 8388608 + 512  */

// 2 SHF + 3 LOP3 per word
__device__ __forceinline__ void extract3(unsigned w, float& fh_, float& fs_, float& fv_) {
    fh_ = __uint_as_float((w >> 20)            | 0x4B000000u);
    fs_ = __uint_as_float(((w >> 10) & 0x3FFu) | 0x4B000000u);
    fv_ = __uint_as_float((w         & 0x3FFu) | 0x4B000000u);
}

__device__ __forceinline__ void process_pixel(const unsigned int* __restrict__ s_t,
                                              float r, float g, float b,
                                              float& o0, float& o1, float& o2) {
    const float EPS = 1e-8f;
    r = __saturatef(r); g = __saturatef(g); b = __saturatef(b);

    // ---- rgb2hsv, hue kept in hp-units (h/60, range [0,6]) ----
    float cmax  = fmaxf(r, fmaxf(g, b));
    float cmin  = fminf(r, fminf(g, b));
    float delta = cmax - cmin;
    float rd = rcp_approx(delta + EPS);

    float q = (g - b) * rd;
    if (q < 0.0f) q += 6.0f;                    // floor-mod 6; may round to 6.0
    float hraw = (cmax == r) ? q
               : (cmax == g) ? (b - r) * rd + 2.0f
                             : (r - g) * rd + 4.0f;
    if (delta <= EPS) hraw = 0.0f;
    float s = (cmax > EPS) ? delta * rcp_approx(cmax + EPS) : 0.0f;
    float v = cmax;

    // ---- lookup indices ----
    float hs  = hraw * 15.0f;                   // [0,90]; 90 iff hraw rounded to 6
    float h0f = floorf(hs);
    float fh  = hs - h0f;
    int i0 = (int)h0f;
    if (i0 >= HD) i0 = 0;                       // hs==90 -> bin 0, fh==0

    float ssv = s * (float)(SD - 1);            // s<~1; over-1 case guarded by clamp
    float s0f = fminf(floorf(ssv), 28.0f);      // j1<=29 always valid
    float fs  = ssv - s0f;
    int j0 = (int)s0f;

    float vsv = v * (float)(VD - 1);
    float v0f = floorf(vsv);
    float fv  = vsv - v0f;                      // v==1: fv==0, +1 hits pad

    int b00 = (i0 * SD + j0) * VD + (int)v0f;
    int di = (i0 == HD - 1) ? -(HD - 1) * SD * VD : SD * VD;
    int b01 = b00 + VD;
    int b10 = b00 + di;
    int b11 = b10 + VD;

    // ---- 8 LDS.32: all 24 corner values ----
    unsigned w00a = s_t[b00], w00b = s_t[b00 + 1];
    unsigned w01a = s_t[b01], w01b = s_t[b01 + 1];
    unsigned w10a = s_t[b10], w10b = s_t[b10 + 1];
    unsigned w11a = s_t[b11], w11b = s_t[b11 + 1];

    float ha00,sa00,va00, hb00,sb00,vb00;
    float ha01,sa01,va01, hb01,sb01,vb01;
    float ha10,sa10,va10, hb10,sb10,vb10;
    float ha11,sa11,va11, hb11,sb11,vb11;
    extract3(w00a, ha00, sa00, va00);  extract3(w00b, hb00, sb00, vb00);
    extract3(w01a, ha01, sa01, va01);  extract3(w01b, hb01, sb01, vb01);
    extract3(w10a, ha10, sa10, va10);  extract3(w10b, hb10, sb10, vb10);
    extract3(w11a, ha11, sa11, va11);  extract3(w11b, hb11, sb11, vb11);

    // exact raw-domain v-lerps: d = fb-fa exact; result = fma(fv, d, fa-bias)
    float hc00 = fmaf(fv, hb00 - ha00, ha00 - HBIAS);
    float hc01 = fmaf(fv, hb01 - ha01, ha01 - HBIAS);
    float hc10 = fmaf(fv, hb10 - ha10, ha10 - HBIAS);
    float hc11 = fmaf(fv, hb11 - ha11, ha11 - HBIAS);
    float sc00 = fmaf(fv, sb00 - sa00, sa00 - SBIAS);
    float sc01 = fmaf(fv, sb01 - sa01, sa01 - SBIAS);
    float sc10 = fmaf(fv, sb10 - sa10, sa10 - SBIAS);
    float sc11 = fmaf(fv, sb11 - sa11, sa11 - SBIAS);
    float vc00 = fmaf(fv, vb00 - va00, va00 - SBIAS);
    float vc01 = fmaf(fv, vb01 - va01, va01 - SBIAS);
    float vc10 = fmaf(fv, vb10 - va10, va10 - SBIAS);
    float vc11 = fmaf(fv, vb11 - va11, va11 - SBIAS);

    // weights: 5 ops
    float w11w = fh * fs;
    float w10w = fh - w11w;          // fh*(1-fs)
    float w01w = fs - w11w;          // (1-fh)*fs
    float w00w = (1.0f - fh) - w01w; // (1-fh)*(1-fs)

    float dhr = w00w * hc00 + w01w * hc01 + w10w * hc10 + w11w * hc11;  // dh*64 (deg)
    float smr = w00w * sc00 + w01w * sc01 + w10w * sc10 + w11w * sc11;  // (sm-1)*1024
    float vmr = w00w * vc00 + w01w * vc01 + w10w * vc10 + w11w * vc11;

    // hue update in hp units: dh_hp = dhr/(64*60)
    float hp = fmaf(dhr, 1.0f / 3840.0f, hraw);
    if (hp < 0.0f)  hp += 6.0f;
    if (hp >= 6.0f) hp -= 6.0f;      // hp in [0,6]
    float s2 = __saturatef(fmaf(smr, s * 0.0009765625f, s));
    float v2 = __saturatef(fmaf(vmr, v * 0.0009765625f, v));

    // ---- hsv2rgb, closed-form (verified identical to select chain per sector):
    //   R = m + c*clamp(|hp-3|-1, 0, 1)
    //   G = m + c*clamp(2-|hp-2|, 0, 1)
    //   B = m + c*clamp(2-|hp-4|, 0, 1)
    float cc = v2 * s2;
    float m  = v2 - cc;
    float tR = __saturatef(fabsf(hp - 3.0f) - 1.0f);
    float tG = __saturatef(2.0f - fabsf(hp - 2.0f));
    float tB = __saturatef(2.0f - fabsf(hp - 4.0f));
    float rr = fmaf(cc, tR, m);
    float gg = fmaf(cc, tG, m);
    float bb = fmaf(cc, tB, m);

    // ---- einsum RGB2XYZ_D50 + clip ----
    o0 = __saturatef(0.7976749f * rr + 0.1351917f * gg + 0.0313534f  * bb);
    o1 = __saturatef(0.2880402f * rr + 0.7118741f * gg + 8.57e-05f   * bb);
    o2 = __saturatef(0.82521f * bb);
}

__global__ __launch_bounds__(1024, 1)
void ProfileLookTableEncoding_kernel(const float* __restrict__ x,
                                     float* __restrict__ out, int nquads) {
    extern __shared__ unsigned int s_t[];

    // Preload packed table into smem, uint4-wide
    {
        const uint4* src = reinterpret_cast<const uint4*>(g_tab);
        uint4* dst = reinterpret_cast<uint4*>(s_t);
        for (int idx = threadIdx.x; idx < NBINS_PAD / 4; idx += 1024)
            dst[idx] = src[idx];
    }
    __syncthreads();

    int stride = gridDim.x * 1024;
    for (int t = blockIdx.x * 1024 + threadIdx.x; t < nquads; t += stride) {
        int p = t * 4;
        int bidx = p >> HW_SHIFT;
        int hw   = p & (HW - 1);
        size_t base = (size_t)bidx * 3 * HW + hw;

        float4 R4 = *reinterpret_cast<const float4*>(x + base);
        float4 G4 = *reinterpret_cast<const float4*>(x + base + HW);
        float4 B4 = *reinterpret_cast<const float4*>(x + base + 2 * HW);

        float rr[4] = {R4.x, R4.y, R4.z, R4.w};
        float gg[4] = {G4.x, G4.y, G4.z, G4.w};
        float bb[4] = {B4.x, B4.y, B4.z, B4.w};
        float o0[4], o1[4], o2[4];

#pragma unroll
        for (int u = 0; u < 4; u++) {
            process_pixel(s_t, rr[u], gg[u], bb[u], o0[u], o1[u], o2[u]);
        }

        float4 O0 = {o0[0], o0[1], o0[2], o0[3]};
        float4 O1 = {o1[0], o1[1], o1[2], o1[3]};
        float4 O2 = {o2[0], o2[1], o2[2], o2[3]};
        *reinterpret_cast<float4*>(out + base)          = O0;
        *reinterpret_cast<float4*>(out + base + HW)     = O1;
        *reinterpret_cast<float4*>(out + base + 2 * HW) = O2;
    }
}

extern "C" void kernel_launch(void* const* d_in, const int* in_sizes, int n_in,
                              void* d_out, int out_size) {
    const float* x   = (const float*)d_in[0];
    const float* lut = (const float*)d_in[1];
    float* out = (float*)d_out;

    prep_kernel<<<(NBINS_PAD + 255) / 256, 256>>>(lut);

    int dev = 0, nsm = 148;
    cudaGetDevice(&dev);
    cudaDeviceGetAttribute(&nsm, cudaDevAttrMultiProcessorCount, dev);

    const int smem_bytes = NBINS_PAD * (int)sizeof(unsigned int);  // 172816 B
    cudaFuncSetAttribute(ProfileLookTableEncoding_kernel,
                         cudaFuncAttributeMaxDynamicSharedMemorySize, smem_bytes);

    int npix = in_sizes[0] / 3;          // 8 * 1024 * 1024
    int nquads = npix / 4;
    ProfileLookTableEncoding_kernel<<<nsm, 1024, smem_bytes>>>(x, out, nquads);
}

// round 11
// speedup vs baseline: 1.2814x; 1.0495x over previous
#include <cuda_runtime.h>

#define HD 90
#define SD 30
#define VD 16
#define NBINS (HD * SD * VD)
#define HW_SHIFT 20
#define HW (1 << HW_SHIFT)

// One packed u32 per bin: [31:20] hue u12 (dh*64 + 2048), [19:10] (sat-1)*1024+512,
// [9:0] (val-1)*1024+512. Table (+pad to uint4 multiple) lives in smem;
// 8 LDS.32 per pixel fetch all 24 trilinear corner values.
#define NBINS_PAD 43204   /* NBINS+1 rounded up to multiple of 4 */
__device__ unsigned int g_tab[NBINS_PAD];

__global__ void prep_kernel(const float* __restrict__ lut) {
    int bin = blockIdx.x * blockDim.x + threadIdx.x;
    if (bin >= NBINS_PAD) return;
    int src = (bin >= NBINS) ? NBINS - 1 : bin;   // pad entries: finite duplicates
    const float* e = lut + (size_t)src * 3;
    int qh = __float2int_rn(e[0] * 64.0f) + 2048;            // step 1/64 deg
    int qs = __float2int_rn((e[1] - 1.0f) * 1024.0f) + 512;  // step 2^-10
    int qv = __float2int_rn((e[2] - 1.0f) * 1024.0f) + 512;
    qh = min(max(qh, 0), 4095);
    qs = min(max(qs, 0), 1023);
    qv = min(max(qv, 0), 1023);
    g_tab[bin] = ((unsigned)qh << 20) | ((unsigned)qs << 10) | (unsigned)qv;
}

__device__ __forceinline__ float rcp_approx(float x) {
    float y;
    asm("rcp.approx.f32 %0, %1;" : "=f"(y) : "f"(x));
    return y;
}

#define HBIAS 8390656.0f   /* 8388608 + 2048 */
#define SBIAS 8389120.0f   /* 8388608 + 512  */

// ---- packed f32x2 helpers (Blackwell FFMA2 path, PTX-only) ----
struct F2 { unsigned long long v; };
__device__ __forceinline__ F2 f2mk(float lo, float hi) {
    F2 r; asm("mov.b64 %0, {%1, %2};" : "=l"(r.v) : "f"(lo), "f"(hi)); return r;
}
__device__ __forceinline__ void f2un(F2 p, float& lo, float& hi) {
    asm("mov.b64 {%0, %1}, %2;" : "=f"(lo), "=f"(hi) : "l"(p.v));
}
__device__ __forceinline__ F2 f2sub(F2 a, F2 b) {
    F2 r; asm("sub.rn.f32x2 %0, %1, %2;" : "=l"(r.v) : "l"(a.v), "l"(b.v)); return r;
}
__device__ __forceinline__ F2 f2mul(F2 a, F2 b) {
    F2 r; asm("mul.rn.f32x2 %0, %1, %2;" : "=l"(r.v) : "l"(a.v), "l"(b.v)); return r;
}
__device__ __forceinline__ F2 f2fma(F2 a, F2 b, F2 c) {
    F2 r; asm("fma.rn.f32x2 %0, %1, %2, %3;" : "=l"(r.v) : "l"(a.v), "l"(b.v), "l"(c.v)); return r;
}

// field extract: ((w>>SH)&MASK)|0x4B000000 -> SHF + single LOP3 (and-or fused)
template<int SH, unsigned MASK>
__device__ __forceinline__ float exf(unsigned w) {
    return __uint_as_float(((w >> SH) & MASK) | 0x4B000000u);
}

// one channel, one pixel-pair: packed trilinear over 4 (i,j)-corners x (k0,k1)
template<int SH, unsigned MASK>
__device__ __forceinline__ F2 chan_lerp(const unsigned* a0, const unsigned* b0,
                                        const unsigned* a1, const unsigned* b1,
                                        F2 fvp, F2 w00p, F2 w01p, F2 w10p, F2 w11p,
                                        F2 bias) {
    F2 A, B, C, acc;
    A = f2mk(exf<SH, MASK>(a0[0]), exf<SH, MASK>(a1[0]));
    B = f2mk(exf<SH, MASK>(b0[0]), exf<SH, MASK>(b1[0]));
    C = f2fma(fvp, f2sub(B, A), f2sub(A, bias));
    acc = f2mul(w00p, C);
    A = f2mk(exf<SH, MASK>(a0[1]), exf<SH, MASK>(a1[1]));
    B = f2mk(exf<SH, MASK>(b0[1]), exf<SH, MASK>(b1[1]));
    C = f2fma(fvp, f2sub(B, A), f2sub(A, bias));
    acc = f2fma(w01p, C, acc);
    A = f2mk(exf<SH, MASK>(a0[2]), exf<SH, MASK>(a1[2]));
    B = f2mk(exf<SH, MASK>(b0[2]), exf<SH, MASK>(b1[2]));
    C = f2fma(fvp, f2sub(B, A), f2sub(A, bias));
    acc = f2fma(w10p, C, acc);
    A = f2mk(exf<SH, MASK>(a0[3]), exf<SH, MASK>(a1[3]));
    B = f2mk(exf<SH, MASK>(b0[3]), exf<SH, MASK>(b1[3]));
    C = f2fma(fvp, f2sub(B, A), f2sub(A, bias));
    acc = f2fma(w11p, C, acc);
    return acc;
}

struct Front {
    float hraw, s, v, fv;
    float w00, w01, w10, w11;
};

__device__ __forceinline__ void front_calc(const unsigned* __restrict__ s_t,
                                           float r, float g, float b, Front& F,
                                           unsigned* wa, unsigned* wb) {
    const float EPS = 1e-8f;
    r = __saturatef(r); g = __saturatef(g); b = __saturatef(b);

    float cmax  = fmaxf(r, fmaxf(g, b));
    float cmin  = fminf(r, fminf(g, b));
    float delta = cmax - cmin;
    float rd = rcp_approx(delta + EPS);

    float q = (g - b) * rd;
    if (q < 0.0f) q += 6.0f;                    // floor-mod 6; may round to 6.0
    float hraw = (cmax == r) ? q
               : (cmax == g) ? (b - r) * rd + 2.0f
                             : (r - g) * rd + 4.0f;
    if (delta <= EPS) hraw = 0.0f;
    float s = (cmax > EPS) ? delta * rcp_approx(cmax + EPS) : 0.0f;
    float v = cmax;

    float hs  = hraw * 15.0f;                   // [0,90]
    float h0f = floorf(hs);
    float fh  = hs - h0f;                       // compute BEFORE wrap
    if (h0f >= 90.0f) h0f = 0.0f;               // hs==90 -> bin 0, fh==0

    float ssv = s * (float)(SD - 1);
    float s0f = fminf(floorf(ssv), 28.0f);      // j1<=29 always valid
    float fs  = ssv - s0f;

    float vsv = v * (float)(VD - 1);
    float v0f = floorf(vsv);
    F.fv = vsv - v0f;                           // v==1: fv==0, +1 hits pad

    // bin index fully in float (exact: < 43200 < 2^24), single F2I
    float bf = fmaf(s0f, 16.0f, v0f);
    bf = fmaf(h0f, 480.0f, bf);
    int b00 = (int)bf;
    int di = (h0f == 89.0f) ? -42720 : 480;     // -(HD-1)*SD*VD : SD*VD

    F.hraw = hraw; F.s = s; F.v = v;
    float w11 = fh * fs;
    F.w11 = w11;
    F.w10 = fh - w11;                 // fh*(1-fs)
    F.w01 = fs - w11;                 // (1-fh)*fs
    F.w00 = (1.0f - fh) - F.w01;      // (1-fh)*(1-fs)

    int b01 = b00 + VD, b10 = b00 + di, b11 = b10 + VD;
    wa[0] = s_t[b00]; wb[0] = s_t[b00 + 1];
    wa[1] = s_t[b01]; wb[1] = s_t[b01 + 1];
    wa[2] = s_t[b10]; wb[2] = s_t[b10 + 1];
    wa[3] = s_t[b11]; wb[3] = s_t[b11 + 1];
}

__device__ __forceinline__ void tail_calc(const Front& F,
                                          float dhr, float smr, float vmr,
                                          float& o0, float& o1, float& o2) {
    float hp = fmaf(dhr, 1.0f / 3840.0f, F.hraw);
    if (hp < 0.0f)  hp += 6.0f;
    if (hp >= 6.0f) hp -= 6.0f;      // hp in [0,6]
    float s2 = __saturatef(fmaf(smr, F.s * 0.0009765625f, F.s));
    float v2 = __saturatef(fmaf(vmr, F.v * 0.0009765625f, F.v));

    // closed-form hsv2rgb (identical to select chain per sector)
    float cc = v2 * s2;
    float m  = v2 - cc;
    float tR = __saturatef(fabsf(hp - 3.0f) - 1.0f);
    float tG = __saturatef(2.0f - fabsf(hp - 2.0f));
    float tB = __saturatef(2.0f - fabsf(hp - 4.0f));
    float rr = fmaf(cc, tR, m);
    float gg = fmaf(cc, tG, m);
    float bb = fmaf(cc, tB, m);

    o0 = __saturatef(0.7976749f * rr + 0.1351917f * gg + 0.0313534f  * bb);
    o1 = __saturatef(0.2880402f * rr + 0.7118741f * gg + 8.57e-05f   * bb);
    o2 = __saturatef(0.82521f * bb);
}

__global__ __launch_bounds__(1024, 1)
void ProfileLookTableEncoding_kernel(const float* __restrict__ x,
                                     float* __restrict__ out, int nquads) {
    extern __shared__ unsigned int s_t[];

    // Preload packed table into smem, uint4-wide
    {
        const uint4* src = reinterpret_cast<const uint4*>(g_tab);
        uint4* dst = reinterpret_cast<uint4*>(s_t);
        for (int idx = threadIdx.x; idx < NBINS_PAD / 4; idx += 1024)
            dst[idx] = src[idx];
    }
    __syncthreads();

    const F2 hbias = f2mk(HBIAS, HBIAS);
    const F2 sbias = f2mk(SBIAS, SBIAS);

    int stride = gridDim.x * 1024;
    for (int t = blockIdx.x * 1024 + threadIdx.x; t < nquads; t += stride) {
        int p = t * 4;
        int bidx = p >> HW_SHIFT;
        int hw   = p & (HW - 1);
        size_t base = (size_t)bidx * 3 * HW + hw;

        float4 R4 = *reinterpret_cast<const float4*>(x + base);
        float4 G4 = *reinterpret_cast<const float4*>(x + base + HW);
        float4 B4 = *reinterpret_cast<const float4*>(x + base + 2 * HW);

        float rr[4] = {R4.x, R4.y, R4.z, R4.w};
        float gg[4] = {G4.x, G4.y, G4.z, G4.w};
        float bb[4] = {B4.x, B4.y, B4.z, B4.w};
        float o0[4], o1[4], o2[4];

#pragma unroll
        for (int pr = 0; pr < 4; pr += 2) {
            Front F0, F1;
            unsigned a0[4], b0[4], a1[4], b1[4];
            front_calc(s_t, rr[pr],     gg[pr],     bb[pr],     F0, a0, b0);
            front_calc(s_t, rr[pr + 1], gg[pr + 1], bb[pr + 1], F1, a1, b1);

            F2 fvp  = f2mk(F0.fv,  F1.fv);
            F2 w00p = f2mk(F0.w00, F1.w00);
            F2 w01p = f2mk(F0.w01, F1.w01);
            F2 w10p = f2mk(F0.w10, F1.w10);
            F2 w11p = f2mk(F0.w11, F1.w11);

            F2 dh2 = chan_lerp<20, 0xFFFu>(a0, b0, a1, b1, fvp, w00p, w01p, w10p, w11p, hbias);
            F2 sm2 = chan_lerp<10, 0x3FFu>(a0, b0, a1, b1, fvp, w00p, w01p, w10p, w11p, sbias);
            F2 vm2 = chan_lerp<0,  0x3FFu>(a0, b0, a1, b1, fvp, w00p, w01p, w10p, w11p, sbias);

            float dhr0, dhr1, smr0, smr1, vmr0, vmr1;
            f2un(dh2, dhr0, dhr1);
            f2un(sm2, smr0, smr1);
            f2un(vm2, vmr0, vmr1);

            tail_calc(F0, dhr0, smr0, vmr0, o0[pr],     o1[pr],     o2[pr]);
            tail_calc(F1, dhr1, smr1, vmr1, o0[pr + 1], o1[pr + 1], o2[pr + 1]);
        }

        float4 O0 = {o0[0], o0[1], o0[2], o0[3]};
        float4 O1 = {o1[0], o1[1], o1[2], o1[3]};
        float4 O2 = {o2[0], o2[1], o2[2], o2[3]};
        *reinterpret_cast<float4*>(out + base)          = O0;
        *reinterpret_cast<float4*>(out + base + HW)     = O1;
        *reinterpret_cast<float4*>(out + base + 2 * HW) = O2;
    }
}

extern "C" void kernel_launch(void* const* d_in, const int* in_sizes, int n_in,
                              void* d_out, int out_size) {
    const float* x   = (const float*)d_in[0];
    const float* lut = (const float*)d_in[1];
    float* out = (float*)d_out;

    prep_kernel<<<(NBINS_PAD + 255) / 256, 256>>>(lut);

    int dev = 0, nsm = 148;
    cudaGetDevice(&dev);
    cudaDeviceGetAttribute(&nsm, cudaDevAttrMultiProcessorCount, dev);

    const int smem_bytes = NBINS_PAD * (int)sizeof(unsigned int);  // 172816 B
    cudaFuncSetAttribute(ProfileLookTableEncoding_kernel,
                         cudaFuncAttributeMaxDynamicSharedMemorySize, smem_bytes);

    int npix = in_sizes[0] / 3;          // 8 * 1024 * 1024
    int nquads = npix / 4;
    ProfileLookTableEncoding_kernel<<<nsm, 1024, smem_bytes>>>(x, out, nquads);
}